// round 3
// baseline (speedup 1.0000x reference)
#include <cuda_runtime.h>
#include <math.h>

#define NIMG 32      // B*G
#define HW   260
#define ES   65      // encoder output spatial
#define DCH  128     // encoder channels
#define S2   162     // correlation channels (81*2)
#define U1   130     // first upsample size
#define HT   258     // texture spatial
#define ED   8
#define HWHW (HW*HW)
#define HTHT (HT*HT)

// ---------------- scratch (device globals; no allocation) ----------------
__device__ float g_fnm[NIMG*ES*ES*DCH];     // [n][y][x][c]
__device__ float g_fpm[NIMG*ES*ES*DCH];
__device__ float g_fpb[NIMG*ES*ES*DCH];
__device__ float g_corr[NIMG*ES*ES*S2];     // [n][y][x][s]
__device__ float g_upcorr[NIMG*U1*U1*S2];   // [n][y][x][s]
__device__ float g_t1[NIMG*U1*U1*ED];       // [n][y][x][oc]
__device__ float g_upt1[NIMG*HW*HW*ED];     // [n][y][x][oc]
__device__ float g_phi[NIMG*HWHW];          // plane
__device__ float g_vort[NIMG*HWHW];         // plane
__device__ float g_velx[NIMG*HTHT];
__device__ float g_vely[NIMG*HTHT];
__device__ float g_wa[NIMG*ED*HTHT];        // warp scratch 1 (f1)
__device__ float g_wb[NIMG*ED*HTHT];        // warp scratch 2 (f2)
__device__ float g_vortk[2][36];

// ---------------- vorticity kernel init ----------------
__global__ void init_vortk_kernel() {
    int i = threadIdx.x;
    if (i < 36) {
        int ky = i / 6, kx = i % 6;
        float yc = (float)ky - 2.5f, xc = (float)kx - 2.5f;
        float r2 = yc*yc + xc*xc;
        float inv = 1.0f / (2.0f * 3.14159265358979323846f * r2);
        g_vortk[0][i] = -yc * inv;   // u component
        g_vortk[1][i] =  xc * inv;   // v component
    }
}

// ---------------- encoder: stride-4 4x4 conv, mask fused ----------------
// in: (4,64,260,260) selected channels; m: (4,260,260); w: (128,8,4,4); out [n][y][x][128]
__global__ void enc_kernel(const float* __restrict__ in, const float* __restrict__ m,
                           const float* __restrict__ w, const float* __restrict__ bias,
                           float* __restrict__ out)
{
    const int PPB = 8;
    __shared__ float patch[PPB][128];
    int n = blockIdx.y;
    int b = n >> 3, g = n & 7;
    int tid = threadIdx.x;          // = oc in compute phase
    int pix0 = blockIdx.x * PPB;

    int ic = tid >> 4, r = tid & 15, ky = r >> 2, kx = r & 3;
    #pragma unroll
    for (int p = 0; p < PPB; p++) {
        int pix = pix0 + p;
        float v = 0.f;
        if (pix < ES*ES) {
            int oy = pix / ES, ox = pix % ES;
            int iy = oy*4 + ky, ix = ox*4 + kx;
            v = in[(((b*64) + g*8 + ic)*HW + iy)*HW + ix] * m[(b*HW + iy)*HW + ix];
        }
        patch[p][tid] = v;
    }
    __syncthreads();

    float acc[PPB];
    float bv = bias[tid];
    #pragma unroll
    for (int p = 0; p < PPB; p++) acc[p] = bv;
    const float4* wr = (const float4*)(w + tid*128);
    #pragma unroll 8
    for (int i = 0; i < 32; i++) {
        float4 wv = wr[i];
        #pragma unroll
        for (int p = 0; p < PPB; p++) {
            acc[p] += patch[p][4*i+0]*wv.x + patch[p][4*i+1]*wv.y
                    + patch[p][4*i+2]*wv.z + patch[p][4*i+3]*wv.w;
        }
    }
    #pragma unroll
    for (int p = 0; p < PPB; p++) {
        int pix = pix0 + p;
        if (pix < ES*ES) out[((n*ES*ES) + pix)*128 + tid] = acc[p];
    }
}

// ---------------- correlation: 81 shifts x {pm,pb} vs nm ----------------
__global__ void corr_kernel(const float* __restrict__ fpm, const float* __restrict__ fpb,
                            const float* __restrict__ fnm, float* __restrict__ corr)
{
    int idx = blockIdx.x * blockDim.x + threadIdx.x;
    const int total = NIMG*ES*ES*S2;
    if (idx >= total) return;
    int s = idx % S2; int t = idx / S2;
    int x = t % ES; t /= ES; int y = t % ES; int n = t / ES;
    const float* f1 = (s < 81) ? fpm : fpb;
    int ss = (s < 81) ? s : s - 81;
    int dy = ss / 9 - 4, dx = ss % 9 - 4;
    int yy = y + dy, xx = x + dx;
    float rr = 0.f;
    if (yy >= 0 && yy < ES && xx >= 0 && xx < ES) {
        const float4* a  = (const float4*)(f1  + ((n*ES*ES) + (y*ES + x))*128);
        const float4* bb = (const float4*)(fnm + ((n*ES*ES) + (yy*ES + xx))*128);
        float acc = 0.f;
        #pragma unroll 8
        for (int i = 0; i < 32; i++) {
            float4 av = a[i], bv = bb[i];
            acc += av.x*bv.x + av.y*bv.y + av.z*bv.z + av.w*bv.w;
        }
        rr = acc * (1.0f/128.0f);
    }
    corr[idx] = rr;
}

// ---------------- up2x (align_corners-style lerp, matches reference) ----------------
__global__ void up2x_kernel(const float* __restrict__ in, float* __restrict__ out,
                            int h, int ch, int nimg)
{
    long total = (long)nimg * (2*h) * (2*h) * ch;
    long idx = (long)blockIdx.x * blockDim.x + threadIdx.x;
    if (idx >= total) return;
    int c = (int)(idx % ch); long t = idx / ch;
    int h2 = 2*h;
    int xo = (int)(t % h2); t /= h2; int yo = (int)(t % h2); int n = (int)(t / h2);
    float fy = (float)(yo * (h-1)) / (float)(h2 - 1);
    float fx = (float)(xo * (h-1)) / (float)(h2 - 1);
    int iy0 = (int)floorf(fy), ix0 = (int)floorf(fx);
    float wy = fy - (float)iy0, wx = fx - (float)ix0;
    int iy1 = min(iy0+1, h-1), ix1 = min(ix0+1, h-1);
    const float* base = in + (long)n*h*h*ch;
    float v00 = base[(iy0*h + ix0)*ch + c];
    float v10 = base[(iy1*h + ix0)*ch + c];
    float v01 = base[(iy0*h + ix1)*ch + c];
    float v11 = base[(iy1*h + ix1)*ch + c];
    out[idx] = (v00*(1.f-wy) + v10*wy)*(1.f-wx) + (v01*(1.f-wy) + v11*wy)*wx;
}

// ---------------- conv1: 3x3, 162 -> 8, + bn + relu ----------------
__global__ void conv1_kernel(const float* __restrict__ in, const float* __restrict__ w,
                             const float* __restrict__ g, const float* __restrict__ bb,
                             float* __restrict__ out)
{
    __shared__ float ws[9*S2*ED];   // [tap][ic][oc] : 46656 B
    __shared__ float scale[ED], bsh[ED];
    int tid = threadIdx.x;
    for (int i = tid; i < ED*S2*9; i += blockDim.x) {
        int kk = i % 9; int t = i / 9; int icc = t % S2; int oc = t / S2;
        ws[kk*(S2*ED) + icc*ED + oc] = w[i];
    }
    if (tid < ED) { scale[tid] = g[tid] * rsqrtf(1.0f + 1e-5f); bsh[tid] = bb[tid]; }
    __syncthreads();

    int pix = blockIdx.x * blockDim.x + tid;
    if (pix >= NIMG*U1*U1) return;
    int x = pix % U1; int t = pix / U1; int y = t % U1; int n = t / U1;

    float acc[ED];
    #pragma unroll
    for (int oc = 0; oc < ED; oc++) acc[oc] = 0.f;

    for (int ky = 0; ky < 3; ky++) {
        int iy = y + ky - 1; if (iy < 0 || iy >= U1) continue;
        for (int kx = 0; kx < 3; kx++) {
            int ix = x + kx - 1; if (ix < 0 || ix >= U1) continue;
            const float* ip = in + ((n*U1*U1) + (iy*U1 + ix))*(long)S2;
            const float* wp = ws + (ky*3 + kx)*(S2*ED);
            #pragma unroll 2
            for (int icc = 0; icc < S2; icc++) {
                float v = ip[icc];
                const float4* w4 = (const float4*)(wp + icc*ED);
                float4 wa = w4[0], wbv = w4[1];
                acc[0] += v*wa.x; acc[1] += v*wa.y; acc[2] += v*wa.z; acc[3] += v*wa.w;
                acc[4] += v*wbv.x; acc[5] += v*wbv.y; acc[6] += v*wbv.z; acc[7] += v*wbv.w;
            }
        }
    }
    float* op = out + (long)pix*ED;
    #pragma unroll
    for (int oc = 0; oc < ED; oc++)
        op[oc] = fmaxf(acc[oc]*scale[oc] + bsh[oc], 0.f);
}

// ---------------- conv2: 3x3, 8 -> 8, + bn + relu + 1x1 + scale ----------------
__global__ void conv2_kernel(const float* __restrict__ in, const float* __restrict__ w,
                             const float* __restrict__ g, const float* __restrict__ bb,
                             const float* __restrict__ ow, const float* __restrict__ ob,
                             const float* __restrict__ wt, float extra,
                             float* __restrict__ out)
{
    __shared__ float ws[9*ED*ED];
    __shared__ float scale[ED], bsh[ED], owsh[ED];
    int tid = threadIdx.x;
    for (int i = tid; i < ED*ED*9; i += blockDim.x) {
        int kk = i % 9; int t = i / 9; int icc = t % ED; int oc = t / ED;
        ws[kk*(ED*ED) + icc*ED + oc] = w[i];
    }
    if (tid < ED) { scale[tid] = g[tid] * rsqrtf(1.0f + 1e-5f); bsh[tid] = bb[tid]; owsh[tid] = ow[tid]; }
    __syncthreads();

    int pix = blockIdx.x * blockDim.x + tid;
    if (pix >= NIMG*HWHW) return;
    int x = pix % HW; int t = pix / HW; int y = t % HW; int n = t / HW;

    float acc[ED];
    #pragma unroll
    for (int oc = 0; oc < ED; oc++) acc[oc] = 0.f;

    #pragma unroll
    for (int ky = 0; ky < 3; ky++) {
        int iy = y + ky - 1; if (iy < 0 || iy >= HW) continue;
        #pragma unroll
        for (int kx = 0; kx < 3; kx++) {
            int ix = x + kx - 1; if (ix < 0 || ix >= HW) continue;
            const float* ip = in + ((long)(n*HWHW) + (iy*HW + ix))*ED;
            const float* wp = ws + (ky*3 + kx)*(ED*ED);
            #pragma unroll
            for (int icc = 0; icc < ED; icc++) {
                float v = ip[icc];
                #pragma unroll
                for (int oc = 0; oc < ED; oc++) acc[oc] += v * wp[icc*ED + oc];
            }
        }
    }
    float rr = 0.f;
    #pragma unroll
    for (int oc = 0; oc < ED; oc++)
        rr += fmaxf(acc[oc]*scale[oc] + bsh[oc], 0.f) * owsh[oc];
    out[pix] = (rr + ob[0]) * wt[0] * extra;
}

// ---------------- velocity: fused helmholtz decode ----------------
__global__ void vel_kernel(const float* __restrict__ phi, const float* __restrict__ vort,
                           float* __restrict__ velx, float* __restrict__ vely)
{
    __shared__ float ku[36], kv[36];
    if (threadIdx.x < 36) { ku[threadIdx.x] = g_vortk[0][threadIdx.x]; kv[threadIdx.x] = g_vortk[1][threadIdx.x]; }
    __syncthreads();
    int idx = blockIdx.x * blockDim.x + threadIdx.x;
    if (idx >= NIMG*HTHT) return;
    int xo = idx % HT; int t = idx / HT; int yo = t % HT; int n = t / HT;
    const float* ph = phi  + (long)n*HWHW;
    const float* vo = vort + (long)n*HWHW;

    float vx = 0.5f*(ph[(yo+1)*HW + xo+2] - ph[(yo+1)*HW + xo]);
    float vy = 0.5f*(ph[(yo+2)*HW + xo+1] - ph[yo*HW + xo+1]);

    // s = vort[:-1,:-1] valid index range [0,258]
    float p[7][7];
    #pragma unroll
    for (int r = 0; r < 7; r++) {
        int a = yo - 3 + r;
        #pragma unroll
        for (int c = 0; c < 7; c++) {
            int bcol = xo - 3 + c;
            p[r][c] = (a >= 0 && a <= 258 && bcol >= 0 && bcol <= 258) ? vo[a*HW + bcol] : 0.f;
        }
    }
    float su = 0.f, sv = 0.f;
    #pragma unroll
    for (int ky = 0; ky < 6; ky++)
        #pragma unroll
        for (int kx = 0; kx < 6; kx++) {
            su += ku[ky*6+kx] * (p[ky+1][kx+1] + p[ky+1][kx]);
            sv += kv[ky*6+kx] * (p[ky+1][kx+1] + p[ky][kx+1]);
        }
    velx[idx] = vx + 0.5f*su;
    vely[idx] = vy + 0.5f*sv;
}

// ---------------- bilinear warp (modes: 0=plain, 1=BFECC combine) ----------------
__global__ void warp_kernel(const float* __restrict__ src, const float* __restrict__ base,
                            const float* __restrict__ velx, const float* __restrict__ vely,
                            float sign, int mode, float* __restrict__ dst)
{
    int idx = blockIdx.x * blockDim.x + threadIdx.x;
    if (idx >= NIMG*HTHT) return;
    int x = idx % HT; int t = idx / HT; int y = t % HT; int n = t / HT;
    float px = (float)x - sign * velx[idx];
    float py = (float)y - sign * vely[idx];
    px = fminf(fmaxf(px, 0.f), (float)(HT-1));
    py = fminf(fmaxf(py, 0.f), (float)(HT-1));
    float fx = floorf(px), fy = floorf(py);
    float wx = px - fx, wy = py - fy;
    int x0 = (int)fx, y0 = (int)fy;
    int x1 = min(x0+1, HT-1), y1 = min(y0+1, HT-1);
    int o00 = y0*HT + x0, o01 = y0*HT + x1, o10 = y1*HT + x0, o11 = y1*HT + x1;
    int sp = y*HT + x;
    #pragma unroll
    for (int c = 0; c < ED; c++) {
        long pbase = (long)(n*ED + c) * HTHT;
        const float* pl = src + pbase;
        float v = (pl[o00]*(1.f-wx) + pl[o01]*wx)*(1.f-wy)
                + (pl[o10]*(1.f-wx) + pl[o11]*wx)*wy;
        float r = (mode == 1) ? (1.5f * base[pbase + sp] - 0.5f * v) : v;
        dst[pbase + sp] = r;
    }
}

// ---------------- per-pixel LayerNorm + MLP(64->64 gelu ->64) + residual, in-place ----------------
__global__ void mlp_kernel(float* __restrict__ out,
                           const float* __restrict__ lng, const float* __restrict__ lnb,
                           const float* __restrict__ w1, const float* __restrict__ b1,
                           const float* __restrict__ w2, const float* __restrict__ b2)
{
    __shared__ float xn[4][64];
    __shared__ float hh[4][64];
    int grp = threadIdx.x >> 6;
    int c = threadIdx.x & 63;
    int pix = blockIdx.x * 4 + grp;        // total = 4*258*258 pixels, exact
    int b = pix / HTHT; int sp = pix % HTHT;
    float* pp = out + (long)(b*64 + c)*HTHT + sp;
    float v = *pp;
    xn[grp][c] = v;
    __syncthreads();
    float mu = 0.f, m2 = 0.f;
    #pragma unroll 8
    for (int i = 0; i < 64; i++) { float tv = xn[grp][i]; mu += tv; m2 += tv*tv; }
    mu *= (1.0f/64.0f); m2 *= (1.0f/64.0f);
    float var = m2 - mu*mu;
    float rs = rsqrtf(var + 1e-5f);
    float xv = (v - mu) * rs * lng[c] + lnb[c];
    __syncthreads();
    xn[grp][c] = xv;
    __syncthreads();
    float h = b1[c];
    const float* wr1 = w1 + c*64;
    #pragma unroll 8
    for (int i = 0; i < 64; i++) h += xn[grp][i] * wr1[i];
    h = 0.5f * h * (1.0f + erff(h * 0.70710678118654752f));
    hh[grp][c] = h;
    __syncthreads();
    float y2 = b2[c];
    const float* wr2 = w2 + c*64;
    #pragma unroll 8
    for (int j = 0; j < 64; j++) y2 += hh[grp][j] * wr2[j];
    *pp = v + y2;
}

// ---------------- launch ----------------
extern "C" void kernel_launch(void* const* d_in, const int* in_sizes, int n_in,
                              void* d_out, int out_size)
{
    const float* prev     = (const float*)d_in[0];
    const float* nxt      = (const float*)d_in[1];
    const float* texture  = (const float*)d_in[2];
    const float* mask     = (const float*)d_in[3];
    const float* boundary = (const float*)d_in[4];
    const float* enc_w    = (const float*)d_in[5];
    const float* enc_b    = (const float*)d_in[6];
    const float* phi_w1   = (const float*)d_in[7];
    const float* phi_g1   = (const float*)d_in[8];
    const float* phi_b1   = (const float*)d_in[9];
    const float* phi_w2   = (const float*)d_in[10];
    const float* phi_g2   = (const float*)d_in[11];
    const float* phi_b2   = (const float*)d_in[12];
    const float* phi_ow   = (const float*)d_in[13];
    const float* phi_ob   = (const float*)d_in[14];
    const float* vor_w1   = (const float*)d_in[15];
    const float* vor_g1   = (const float*)d_in[16];
    const float* vor_b1   = (const float*)d_in[17];
    const float* vor_w2   = (const float*)d_in[18];
    const float* vor_g2   = (const float*)d_in[19];
    const float* vor_b2   = (const float*)d_in[20];
    const float* vor_ow   = (const float*)d_in[21];
    const float* vor_ob   = (const float*)d_in[22];
    const float* phi_wt   = (const float*)d_in[23];
    const float* vor_wt   = (const float*)d_in[24];
    const float* ln_g     = (const float*)d_in[25];
    const float* ln_b     = (const float*)d_in[26];
    const float* fc1_w    = (const float*)d_in[27];
    const float* fc1_b    = (const float*)d_in[28];
    const float* fc2_w    = (const float*)d_in[29];
    const float* fc2_b    = (const float*)d_in[30];
    float* outp = (float*)d_out;

    float *fnm, *fpm, *fpb, *corr, *upcorr, *t1, *upt1, *phi, *vort, *velx, *vely, *wa, *wb;
    cudaGetSymbolAddress((void**)&fnm,    g_fnm);
    cudaGetSymbolAddress((void**)&fpm,    g_fpm);
    cudaGetSymbolAddress((void**)&fpb,    g_fpb);
    cudaGetSymbolAddress((void**)&corr,   g_corr);
    cudaGetSymbolAddress((void**)&upcorr, g_upcorr);
    cudaGetSymbolAddress((void**)&t1,     g_t1);
    cudaGetSymbolAddress((void**)&upt1,   g_upt1);
    cudaGetSymbolAddress((void**)&phi,    g_phi);
    cudaGetSymbolAddress((void**)&vort,   g_vort);
    cudaGetSymbolAddress((void**)&velx,   g_velx);
    cudaGetSymbolAddress((void**)&vely,   g_vely);
    cudaGetSymbolAddress((void**)&wa,     g_wa);
    cudaGetSymbolAddress((void**)&wb,     g_wb);

    init_vortk_kernel<<<1, 64>>>();

    dim3 egrid((ES*ES + 7)/8, NIMG);
    enc_kernel<<<egrid, 128>>>(nxt,  mask,     enc_w, enc_b, fnm);
    enc_kernel<<<egrid, 128>>>(prev, mask,     enc_w, enc_b, fpm);
    enc_kernel<<<egrid, 128>>>(prev, boundary, enc_w, enc_b, fpb);

    {
        int total = NIMG*ES*ES*S2;
        corr_kernel<<<(total + 255)/256, 256>>>(fpm, fpb, fnm, corr);
    }
    {
        long total = (long)NIMG*U1*U1*S2;
        up2x_kernel<<<(unsigned)((total + 255)/256), 256>>>(corr, upcorr, ES, S2, NIMG);
    }

    int c1blocks = (NIMG*U1*U1 + 127)/128;
    int c2blocks = (NIMG*HWHW + 255)/256;
    long u2total = (long)NIMG*HWHW*ED;

    // phi branch
    conv1_kernel<<<c1blocks, 128>>>(upcorr, phi_w1, phi_g1, phi_b1, t1);
    up2x_kernel<<<(unsigned)((u2total + 255)/256), 256>>>(t1, upt1, U1, ED, NIMG);
    conv2_kernel<<<c2blocks, 256>>>(upt1, phi_w2, phi_g2, phi_b2, phi_ow, phi_ob, phi_wt, 1.0f, phi);

    // vorticity branch
    conv1_kernel<<<c1blocks, 128>>>(upcorr, vor_w1, vor_g1, vor_b1, t1);
    up2x_kernel<<<(unsigned)((u2total + 255)/256), 256>>>(t1, upt1, U1, ED, NIMG);
    conv2_kernel<<<c2blocks, 256>>>(upt1, vor_w2, vor_g2, vor_b2, vor_ow, vor_ob, vor_wt, 260.0f, vort);

    int vblocks = (NIMG*HTHT + 255)/256;
    vel_kernel<<<vblocks, 256>>>(phi, vort, velx, vely);

    // BFECC: f1 = warp(tex,+1); f2 = 1.5*tex - 0.5*warp(f1,-1); pred = warp(f2,+1)
    warp_kernel<<<vblocks, 256>>>(texture, nullptr,  velx, vely,  1.0f, 0, wa);
    warp_kernel<<<vblocks, 256>>>(wa,      texture,  velx, vely, -1.0f, 1, wb);
    warp_kernel<<<vblocks, 256>>>(wb,      nullptr,  velx, vely,  1.0f, 0, outp);

    mlp_kernel<<<HTHT, 256>>>(outp, ln_g, ln_b, fc1_w, fc1_b, fc2_w, fc2_b);
}

// round 4
// speedup vs baseline: 3.4923x; 3.4923x over previous
#include <cuda_runtime.h>
#include <math.h>

#define NIMG 32      // B*G
#define HW   260
#define ES   65      // encoder output spatial
#define DCH  128     // encoder channels
#define S2   162     // correlation channels (81*2)
#define U1   130     // first upsample size
#define HT   258     // texture spatial
#define ED   8
#define HWHW (HW*HW)
#define HTHT (HT*HT)
#define CORR_PAD 132

// ---------------- scratch (device globals; no allocation) ----------------
__device__ float g_fnm[NIMG*ES*ES*DCH];     // [n][y][x][c]
__device__ float g_fpm[NIMG*ES*ES*DCH];
__device__ float g_fpb[NIMG*ES*ES*DCH];
__device__ float g_corr[NIMG*ES*ES*S2];     // [n][y][x][s]
__device__ float g_upcorr[NIMG*U1*U1*S2];   // [n][y][x][s]
__device__ float g_t1[NIMG*U1*U1*ED];       // [n][y][x][oc]
__device__ float g_upt1[NIMG*HW*HW*ED];     // [n][y][x][oc]
__device__ float g_phi[NIMG*HWHW];          // plane
__device__ float g_vort[NIMG*HWHW];         // plane
__device__ float g_velx[NIMG*HTHT];
__device__ float g_vely[NIMG*HTHT];
__device__ float g_wa[NIMG*ED*HTHT];        // warp scratch 1 (f1)
__device__ float g_wb[NIMG*ED*HTHT];        // warp scratch 2 (f2)
__device__ float g_vortk[2][36];

// ---------------- vorticity kernel init ----------------
__global__ void init_vortk_kernel() {
    int i = threadIdx.x;
    if (i < 36) {
        int ky = i / 6, kx = i % 6;
        float yc = (float)ky - 2.5f, xc = (float)kx - 2.5f;
        float r2 = yc*yc + xc*xc;
        float inv = 1.0f / (2.0f * 3.14159265358979323846f * r2);
        g_vortk[0][i] = -yc * inv;   // u component
        g_vortk[1][i] =  xc * inv;   // v component
    }
}

// ---------------- encoder: stride-4 4x4 conv, mask fused, 16 px/block ----------------
__global__ __launch_bounds__(128) void enc_kernel(
        const float* __restrict__ in, const float* __restrict__ m,
        const float* __restrict__ w, const float* __restrict__ bias,
        float* __restrict__ out)
{
    const int PPB = 16;
    __shared__ float patch[PPB][128];
    int n = blockIdx.y;
    int b = n >> 3, g = n & 7;
    int tid = threadIdx.x;          // = oc in compute phase
    int pix0 = blockIdx.x * PPB;

    int ic = tid >> 4, r = tid & 15, ky = r >> 2, kx = r & 3;
    const float* inb = in + ((long)(b*64 + g*8 + ic))*HWHW;
    const float* mb  = m  + (long)b*HWHW;
    #pragma unroll
    for (int p = 0; p < PPB; p++) {
        int pix = pix0 + p;
        float v = 0.f;
        if (pix < ES*ES) {
            int oy = pix / ES, ox = pix % ES;
            int iy = oy*4 + ky, ix = ox*4 + kx;
            v = inb[iy*HW + ix] * mb[iy*HW + ix];
        }
        patch[p][tid] = v;
    }
    __syncthreads();

    float acc[PPB];
    float bv = bias[tid];
    #pragma unroll
    for (int p = 0; p < PPB; p++) acc[p] = bv;
    const float4* wr = (const float4*)(w + tid*128);
    #pragma unroll 4
    for (int i = 0; i < 32; i++) {
        float4 wv = wr[i];
        #pragma unroll
        for (int p = 0; p < PPB; p++) {
            float4 xv = ((const float4*)patch[p])[i];
            acc[p] += xv.x*wv.x + xv.y*wv.y + xv.z*wv.z + xv.w*wv.w;
        }
    }
    #pragma unroll
    for (int p = 0; p < PPB; p++) {
        int pix = pix0 + p;
        if (pix < ES*ES) out[((long)n*ES*ES + pix)*128 + tid] = acc[p];
    }
}

// ---------------- correlation: block per pixel, smem-staged rows ----------------
__global__ __launch_bounds__(256) void corr_kernel(
        const float* __restrict__ fpm, const float* __restrict__ fpb,
        const float* __restrict__ fnm, float* __restrict__ corr)
{
    __shared__ float bsm[81*CORR_PAD];   // [row][ch], padded row stride
    __shared__ float apm[128], apb[128];
    int blk = blockIdx.x;                // n*4225 + y*65 + x
    int tid = threadIdx.x;
    int n = blk / (ES*ES);
    int rem = blk % (ES*ES);
    int y = rem / ES, x = rem % ES;

    if (tid < 32) {
        ((float4*)apm)[tid] = ((const float4*)(fpm + (long)blk*128))[tid];
    } else if (tid < 64) {
        ((float4*)apb)[tid-32] = ((const float4*)(fpb + (long)blk*128))[tid-32];
    }
    for (int i = tid; i < 81*32; i += 256) {
        int row = i >> 5, c4 = i & 31;
        int dy = row / 9 - 4, dx = row % 9 - 4;
        int yy = y + dy, xx = x + dx;
        float4 val = make_float4(0.f, 0.f, 0.f, 0.f);
        if (yy >= 0 && yy < ES && xx >= 0 && xx < ES)
            val = ((const float4*)(fnm + ((long)n*ES*ES + yy*ES + xx)*128))[c4];
        *((float4*)(bsm + row*CORR_PAD + c4*4)) = val;
    }
    __syncthreads();

    if (tid < S2) {
        int srow = (tid < 81) ? tid : tid - 81;
        const float4* a4 = (const float4*)((tid < 81) ? apm : apb);
        const float4* b4 = (const float4*)(bsm + srow*CORR_PAD);
        float acc = 0.f;
        #pragma unroll 8
        for (int i = 0; i < 32; i++) {
            float4 av = a4[i], bv = b4[i];
            acc += av.x*bv.x + av.y*bv.y + av.z*bv.z + av.w*bv.w;
        }
        corr[(long)blk*S2 + tid] = acc * (1.0f/128.0f);
    }
}

// ---------------- up2x (align_corners-style lerp, matches reference) ----------------
__global__ void up2x_kernel(const float* __restrict__ in, float* __restrict__ out,
                            int h, int ch, int nimg)
{
    long total = (long)nimg * (2*h) * (2*h) * ch;
    long idx = (long)blockIdx.x * blockDim.x + threadIdx.x;
    if (idx >= total) return;
    int c = (int)(idx % ch); long t = idx / ch;
    int h2 = 2*h;
    int xo = (int)(t % h2); t /= h2; int yo = (int)(t % h2); int n = (int)(t / h2);
    float fy = (float)(yo * (h-1)) / (float)(h2 - 1);
    float fx = (float)(xo * (h-1)) / (float)(h2 - 1);
    int iy0 = (int)floorf(fy), ix0 = (int)floorf(fx);
    float wy = fy - (float)iy0, wx = fx - (float)ix0;
    int iy1 = min(iy0+1, h-1), ix1 = min(ix0+1, h-1);
    const float* base = in + (long)n*h*h*ch;
    float v00 = base[(iy0*h + ix0)*ch + c];
    float v10 = base[(iy1*h + ix0)*ch + c];
    float v01 = base[(iy0*h + ix1)*ch + c];
    float v11 = base[(iy1*h + ix1)*ch + c];
    out[idx] = (v00*(1.f-wy) + v10*wy)*(1.f-wx) + (v01*(1.f-wy) + v11*wy)*wx;
}

// ---------------- conv1: 3x3, 162 -> 8, + bn + relu; warp per 4 pixels ----------------
__global__ __launch_bounds__(256) void conv1_kernel(
        const float* __restrict__ in, const float* __restrict__ w,
        const float* __restrict__ g, const float* __restrict__ bb,
        float* __restrict__ out)
{
    __shared__ float ws[9*8*S2];     // [kk][oc][ic]
    __shared__ float scale[ED], bsh[ED];
    int tid = threadIdx.x;
    for (int i = tid; i < 9*8*S2; i += 256) {
        int ic = i % S2; int t = i / S2; int oc = t & 7; int kk = t >> 3;
        ws[i] = w[(oc*S2 + ic)*9 + kk];
    }
    if (tid < ED) { scale[tid] = g[tid] * rsqrtf(1.0f + 1e-5f); bsh[tid] = bb[tid]; }
    __syncthreads();

    int lane = tid & 31;
    int pix0 = (blockIdx.x*8 + (tid >> 5))*4;

    float acc[4][8];
    #pragma unroll
    for (int p = 0; p < 4; p++)
        #pragma unroll
        for (int o = 0; o < 8; o++) acc[p][o] = 0.f;

    int xs[4], ys[4]; long base[4];
    #pragma unroll
    for (int p = 0; p < 4; p++) {
        int pix = pix0 + p;
        xs[p] = pix % U1;
        int t2 = pix / U1;
        ys[p] = t2 % U1;
        base[p] = (long)(t2 / U1) * (U1*U1);
    }

    #pragma unroll
    for (int ky = 0; ky < 3; ky++)
    #pragma unroll
    for (int kx = 0; kx < 3; kx++) {
        const float* wpt = ws + (ky*3 + kx)*(8*S2);
        #pragma unroll
        for (int jp = 0; jp < 3; jp++) {
            int ic2 = jp*32 + lane;
            bool act = ic2 < 81;              // 81 float2 per channel row
            int ic2c = act ? ic2 : 0;
            float2 v[4];
            #pragma unroll
            for (int p = 0; p < 4; p++) {
                int iy = ys[p] + ky - 1, ix = xs[p] + kx - 1;
                bool ok = act && iy >= 0 && iy < U1 && ix >= 0 && ix < U1;
                v[p] = ok ? ((const float2*)(in + (base[p] + iy*U1 + ix)*(long)S2))[ic2c]
                          : make_float2(0.f, 0.f);
            }
            #pragma unroll
            for (int half = 0; half < 2; half++) {
                float2 wv[4];
                #pragma unroll
                for (int o = 0; o < 4; o++)
                    wv[o] = ((const float2*)(wpt + (half*4 + o)*S2))[ic2c];
                #pragma unroll
                for (int p = 0; p < 4; p++)
                    #pragma unroll
                    for (int o = 0; o < 4; o++)
                        acc[p][half*4 + o] += v[p].x*wv[o].x + v[p].y*wv[o].y;
            }
        }
    }
    // butterfly reduce across lanes (all lanes end with full sums)
    #pragma unroll
    for (int off = 16; off > 0; off >>= 1)
        #pragma unroll
        for (int p = 0; p < 4; p++)
            #pragma unroll
            for (int o = 0; o < 8; o++)
                acc[p][o] += __shfl_xor_sync(0xffffffffu, acc[p][o], off);

    #pragma unroll
    for (int p = 0; p < 4; p++) {
        if (lane == p) {
            float* op = out + (long)(pix0 + p)*ED;
            #pragma unroll
            for (int o = 0; o < 8; o++)
                op[o] = fmaxf(acc[p][o]*scale[o] + bsh[o], 0.f);
        }
    }
}

// ---------------- conv2: 3x3, 8 -> 8, + bn + relu + 1x1 + scale ----------------
__global__ __launch_bounds__(256) void conv2_kernel(
        const float* __restrict__ in, const float* __restrict__ w,
        const float* __restrict__ g, const float* __restrict__ bb,
        const float* __restrict__ ow, const float* __restrict__ ob,
        const float* __restrict__ wt, float extra,
        float* __restrict__ out)
{
    __shared__ float ws[9*64];       // [kk][oc][ic]
    __shared__ float scale[ED], bsh[ED], owsh[ED];
    int tid = threadIdx.x;
    for (int i = tid; i < 576; i += 256) {
        int ic = i & 7, oc = (i >> 3) & 7, kk = i >> 6;
        ws[i] = w[(oc*8 + ic)*9 + kk];
    }
    if (tid < ED) { scale[tid] = g[tid] * rsqrtf(1.0f + 1e-5f); bsh[tid] = bb[tid]; owsh[tid] = ow[tid]; }
    __syncthreads();

    int pix = blockIdx.x * 256 + tid;
    int x = pix % HW; int t = pix / HW; int y = t % HW; int n = t / HW;

    float acc[ED];
    #pragma unroll
    for (int oc = 0; oc < ED; oc++) acc[oc] = 0.f;

    #pragma unroll
    for (int ky = 0; ky < 3; ky++) {
        int iy = y + ky - 1; if (iy < 0 || iy >= HW) continue;
        #pragma unroll
        for (int kx = 0; kx < 3; kx++) {
            int ix = x + kx - 1; if (ix < 0 || ix >= HW) continue;
            const float4* ip4 = (const float4*)(in + ((long)n*HWHW + iy*HW + ix)*ED);
            float4 s0 = ip4[0], s1 = ip4[1];
            const float* wp = ws + (ky*3 + kx)*64;
            #pragma unroll
            for (int oc = 0; oc < ED; oc++) {
                const float4* wq = (const float4*)(wp + oc*8);
                float4 w0 = wq[0], w1 = wq[1];
                acc[oc] += s0.x*w0.x + s0.y*w0.y + s0.z*w0.z + s0.w*w0.w
                         + s1.x*w1.x + s1.y*w1.y + s1.z*w1.z + s1.w*w1.w;
            }
        }
    }
    float rr = 0.f;
    #pragma unroll
    for (int oc = 0; oc < ED; oc++)
        rr += fmaxf(acc[oc]*scale[oc] + bsh[oc], 0.f) * owsh[oc];
    out[pix] = (rr + ob[0]) * wt[0] * extra;
}

// ---------------- velocity: fused helmholtz decode ----------------
__global__ void vel_kernel(const float* __restrict__ phi, const float* __restrict__ vort,
                           float* __restrict__ velx, float* __restrict__ vely)
{
    __shared__ float ku[36], kv[36];
    if (threadIdx.x < 36) { ku[threadIdx.x] = g_vortk[0][threadIdx.x]; kv[threadIdx.x] = g_vortk[1][threadIdx.x]; }
    __syncthreads();
    int idx = blockIdx.x * blockDim.x + threadIdx.x;
    if (idx >= NIMG*HTHT) return;
    int xo = idx % HT; int t = idx / HT; int yo = t % HT; int n = t / HT;
    const float* ph = phi  + (long)n*HWHW;
    const float* vo = vort + (long)n*HWHW;

    float vx = 0.5f*(ph[(yo+1)*HW + xo+2] - ph[(yo+1)*HW + xo]);
    float vy = 0.5f*(ph[(yo+2)*HW + xo+1] - ph[yo*HW + xo+1]);

    float p[7][7];
    #pragma unroll
    for (int r = 0; r < 7; r++) {
        int a = yo - 3 + r;
        #pragma unroll
        for (int c = 0; c < 7; c++) {
            int bcol = xo - 3 + c;
            p[r][c] = (a >= 0 && a <= 258 && bcol >= 0 && bcol <= 258) ? vo[a*HW + bcol] : 0.f;
        }
    }
    float su = 0.f, sv = 0.f;
    #pragma unroll
    for (int ky = 0; ky < 6; ky++)
        #pragma unroll
        for (int kx = 0; kx < 6; kx++) {
            su += ku[ky*6+kx] * (p[ky+1][kx+1] + p[ky+1][kx]);
            sv += kv[ky*6+kx] * (p[ky+1][kx+1] + p[ky][kx+1]);
        }
    velx[idx] = vx + 0.5f*su;
    vely[idx] = vy + 0.5f*sv;
}

// ---------------- bilinear warp (modes: 0=plain, 1=BFECC combine) ----------------
__global__ void warp_kernel(const float* __restrict__ src, const float* __restrict__ base,
                            const float* __restrict__ velx, const float* __restrict__ vely,
                            float sign, int mode, float* __restrict__ dst)
{
    int idx = blockIdx.x * blockDim.x + threadIdx.x;
    if (idx >= NIMG*HTHT) return;
    int x = idx % HT; int t = idx / HT; int y = t % HT; int n = t / HT;
    float px = (float)x - sign * velx[idx];
    float py = (float)y - sign * vely[idx];
    px = fminf(fmaxf(px, 0.f), (float)(HT-1));
    py = fminf(fmaxf(py, 0.f), (float)(HT-1));
    float fx = floorf(px), fy = floorf(py);
    float wx = px - fx, wy = py - fy;
    int x0 = (int)fx, y0 = (int)fy;
    int x1 = min(x0+1, HT-1), y1 = min(y0+1, HT-1);
    int o00 = y0*HT + x0, o01 = y0*HT + x1, o10 = y1*HT + x0, o11 = y1*HT + x1;
    int sp = y*HT + x;
    #pragma unroll
    for (int c = 0; c < ED; c++) {
        long pbase = (long)(n*ED + c) * HTHT;
        const float* pl = src + pbase;
        float v = (pl[o00]*(1.f-wx) + pl[o01]*wx)*(1.f-wy)
                + (pl[o10]*(1.f-wx) + pl[o11]*wx)*wy;
        float r = (mode == 1) ? (1.5f * base[pbase + sp] - 0.5f * v) : v;
        dst[pbase + sp] = r;
    }
}

// ---------------- per-pixel LayerNorm + MLP(64->gelu->64) + residual, in-place ----------------
__global__ __launch_bounds__(256) void mlp_kernel(float* __restrict__ out,
                           const float* __restrict__ lng, const float* __restrict__ lnb,
                           const float* __restrict__ w1, const float* __restrict__ b1,
                           const float* __restrict__ w2, const float* __restrict__ b2)
{
    __shared__ float w1s[64*65], w2s[64*65];   // transposed, stride-65 (bank-safe)
    __shared__ float xn[8][64];
    __shared__ float hh[8][64];
    int tid = threadIdx.x;
    for (int i = tid; i < 4096; i += 256) {
        int r = i >> 6, cc = i & 63;           // r = out idx, cc = in idx
        w1s[cc*65 + r] = w1[i];
        w2s[cc*65 + r] = w2[i];
    }
    int c  = tid & 63;
    int g0 = (tid >> 6) * 2;                   // 2 pixels per thread, 8 per block
    float lg = lng[c], lb = lnb[c], b1v = b1[c], b2v = b2[c];

    float v[2]; float* pp[2];
    #pragma unroll
    for (int k = 0; k < 2; k++) {
        int pix = blockIdx.x*8 + g0 + k;
        int bi = pix / HTHT, sp = pix % HTHT;
        pp[k] = out + ((long)(bi*64 + c))*HTHT + sp;
        v[k] = *pp[k];
    }
    __syncthreads();
    xn[g0][c] = v[0]; xn[g0+1][c] = v[1];
    __syncthreads();
    float xv[2];
    #pragma unroll
    for (int k = 0; k < 2; k++) {
        float mu = 0.f, m2 = 0.f;
        #pragma unroll 8
        for (int i = 0; i < 64; i++) { float tv = xn[g0+k][i]; mu += tv; m2 += tv*tv; }
        mu *= (1.0f/64.0f); m2 *= (1.0f/64.0f);
        float rs = rsqrtf(m2 - mu*mu + 1e-5f);
        xv[k] = (v[k] - mu)*rs*lg + lb;
    }
    __syncthreads();
    xn[g0][c] = xv[0]; xn[g0+1][c] = xv[1];
    __syncthreads();
    float h0 = b1v, h1 = b1v;
    #pragma unroll 8
    for (int i = 0; i < 64; i++) {
        float wv = w1s[i*65 + c];
        h0 += xn[g0][i]*wv;
        h1 += xn[g0+1][i]*wv;
    }
    h0 = 0.5f*h0*(1.0f + erff(h0*0.70710678118654752f));
    h1 = 0.5f*h1*(1.0f + erff(h1*0.70710678118654752f));
    hh[g0][c] = h0; hh[g0+1][c] = h1;
    __syncthreads();
    float y0 = b2v, y1 = b2v;
    #pragma unroll 8
    for (int j = 0; j < 64; j++) {
        float wv = w2s[j*65 + c];
        y0 += hh[g0][j]*wv;
        y1 += hh[g0+1][j]*wv;
    }
    *pp[0] = v[0] + y0;
    *pp[1] = v[1] + y1;
}

// ---------------- launch ----------------
extern "C" void kernel_launch(void* const* d_in, const int* in_sizes, int n_in,
                              void* d_out, int out_size)
{
    const float* prev     = (const float*)d_in[0];
    const float* nxt      = (const float*)d_in[1];
    const float* texture  = (const float*)d_in[2];
    const float* mask     = (const float*)d_in[3];
    const float* boundary = (const float*)d_in[4];
    const float* enc_w    = (const float*)d_in[5];
    const float* enc_b    = (const float*)d_in[6];
    const float* phi_w1   = (const float*)d_in[7];
    const float* phi_g1   = (const float*)d_in[8];
    const float* phi_b1   = (const float*)d_in[9];
    const float* phi_w2   = (const float*)d_in[10];
    const float* phi_g2   = (const float*)d_in[11];
    const float* phi_b2   = (const float*)d_in[12];
    const float* phi_ow   = (const float*)d_in[13];
    const float* phi_ob   = (const float*)d_in[14];
    const float* vor_w1   = (const float*)d_in[15];
    const float* vor_g1   = (const float*)d_in[16];
    const float* vor_b1   = (const float*)d_in[17];
    const float* vor_w2   = (const float*)d_in[18];
    const float* vor_g2   = (const float*)d_in[19];
    const float* vor_b2   = (const float*)d_in[20];
    const float* vor_ow   = (const float*)d_in[21];
    const float* vor_ob   = (const float*)d_in[22];
    const float* phi_wt   = (const float*)d_in[23];
    const float* vor_wt   = (const float*)d_in[24];
    const float* ln_g     = (const float*)d_in[25];
    const float* ln_b     = (const float*)d_in[26];
    const float* fc1_w    = (const float*)d_in[27];
    const float* fc1_b    = (const float*)d_in[28];
    const float* fc2_w    = (const float*)d_in[29];
    const float* fc2_b    = (const float*)d_in[30];
    float* outp = (float*)d_out;

    float *fnm, *fpm, *fpb, *corr, *upcorr, *t1, *upt1, *phi, *vort, *velx, *vely, *wa, *wb;
    cudaGetSymbolAddress((void**)&fnm,    g_fnm);
    cudaGetSymbolAddress((void**)&fpm,    g_fpm);
    cudaGetSymbolAddress((void**)&fpb,    g_fpb);
    cudaGetSymbolAddress((void**)&corr,   g_corr);
    cudaGetSymbolAddress((void**)&upcorr, g_upcorr);
    cudaGetSymbolAddress((void**)&t1,     g_t1);
    cudaGetSymbolAddress((void**)&upt1,   g_upt1);
    cudaGetSymbolAddress((void**)&phi,    g_phi);
    cudaGetSymbolAddress((void**)&vort,   g_vort);
    cudaGetSymbolAddress((void**)&velx,   g_velx);
    cudaGetSymbolAddress((void**)&vely,   g_vely);
    cudaGetSymbolAddress((void**)&wa,     g_wa);
    cudaGetSymbolAddress((void**)&wb,     g_wb);

    init_vortk_kernel<<<1, 64>>>();

    dim3 egrid((ES*ES + 15)/16, NIMG);
    enc_kernel<<<egrid, 128>>>(nxt,  mask,     enc_w, enc_b, fnm);
    enc_kernel<<<egrid, 128>>>(prev, mask,     enc_w, enc_b, fpm);
    enc_kernel<<<egrid, 128>>>(prev, boundary, enc_w, enc_b, fpb);

    corr_kernel<<<NIMG*ES*ES, 256>>>(fpm, fpb, fnm, corr);

    {
        long total = (long)NIMG*U1*U1*S2;
        up2x_kernel<<<(unsigned)((total + 255)/256), 256>>>(corr, upcorr, ES, S2, NIMG);
    }

    int c1blocks = (NIMG*U1*U1) / 32;        // 4 px/warp * 8 warps = 32 px/block (exact)
    int c2blocks = (NIMG*HWHW) / 256;        // exact
    long u2total = (long)NIMG*HWHW*ED;

    // phi branch
    conv1_kernel<<<c1blocks, 256>>>(upcorr, phi_w1, phi_g1, phi_b1, t1);
    up2x_kernel<<<(unsigned)((u2total + 255)/256), 256>>>(t1, upt1, U1, ED, NIMG);
    conv2_kernel<<<c2blocks, 256>>>(upt1, phi_w2, phi_g2, phi_b2, phi_ow, phi_ob, phi_wt, 1.0f, phi);

    // vorticity branch
    conv1_kernel<<<c1blocks, 256>>>(upcorr, vor_w1, vor_g1, vor_b1, t1);
    up2x_kernel<<<(unsigned)((u2total + 255)/256), 256>>>(t1, upt1, U1, ED, NIMG);
    conv2_kernel<<<c2blocks, 256>>>(upt1, vor_w2, vor_g2, vor_b2, vor_ow, vor_ob, vor_wt, 260.0f, vort);

    int vblocks = (NIMG*HTHT + 255)/256;
    vel_kernel<<<vblocks, 256>>>(phi, vort, velx, vely);

    // BFECC: f1 = warp(tex,+1); f2 = 1.5*tex - 0.5*warp(f1,-1); pred = warp(f2,+1)
    warp_kernel<<<vblocks, 256>>>(texture, nullptr,  velx, vely,  1.0f, 0, wa);
    warp_kernel<<<vblocks, 256>>>(wa,      texture,  velx, vely, -1.0f, 1, wb);
    warp_kernel<<<vblocks, 256>>>(wb,      nullptr,  velx, vely,  1.0f, 0, outp);

    mlp_kernel<<<(4*HTHT)/8, 256>>>(outp, ln_g, ln_b, fc1_w, fc1_b, fc2_w, fc2_b);
}